// round 5
// baseline (speedup 1.0000x reference)
#include <cuda_runtime.h>
#include <cuda_bf16.h>
#include <math.h>
#include <stdint.h>

// Problem dims
#define BB 8
#define LL_ 512
#define DD 768
#define HH 12
#define DKK 64
#define MTOT 96      // BB*HH
#define NN 512

// Output layout (flattened tuple concat)
#define OFF_CTX 0
#define OFF_D   37748736
#define OFF_D0  62914560
#define OFF_LOSS 62963712

// ---------------- scratch (device globals; no allocations allowed) ----------------
__device__ float g_q[BB * LL_ * DD];
__device__ float g_k[BB * LL_ * DD];
__device__ float g_R[BB * LL_];
__device__ float g_m[BB * LL_];
__device__ float g_A[MTOT * NN * NN];     // exp(scores)
__device__ float g_LLm[MTOT * NN * NN];   // Laplacian -> becomes inverse in place
__device__ float g_Fcol[MTOT * NN * 64];  // saved column block for GJ step
__device__ float g_colsum[MTOT * NN];
__device__ float g_diag[MTOT * NN];
__device__ float g_bce[BB * LL_];

// ===================== mma.sync helpers (HMMA path; compute_103-safe) =====================
__device__ __forceinline__ uint32_t smem_u32(const void* p) {
    uint32_t a;
    asm("{ .reg .u64 t; cvta.to.shared.u64 t, %1; cvt.u32.u64 %0, t; }"
        : "=r"(a) : "l"(p));
    return a;
}

__device__ __forceinline__ void ldsm4t(uint32_t* r, uint32_t addr) {
    asm volatile("ldmatrix.sync.aligned.m8n8.x4.trans.shared.b16 {%0,%1,%2,%3}, [%4];"
                 : "=r"(r[0]), "=r"(r[1]), "=r"(r[2]), "=r"(r[3]) : "r"(addr));
}

__device__ __forceinline__ void mma16816(float* c, const uint32_t* a,
                                         uint32_t b0, uint32_t b1) {
    asm volatile("mma.sync.aligned.m16n8k16.row.col.f32.bf16.bf16.f32 "
                 "{%0,%1,%2,%3}, {%4,%5,%6,%7}, {%8,%9}, {%0,%1,%2,%3};"
                 : "+f"(c[0]), "+f"(c[1]), "+f"(c[2]), "+f"(c[3])
                 : "r"(a[0]), "r"(a[1]), "r"(a[2]), "r"(a[3]), "r"(b0), "r"(b1));
}

__device__ __forceinline__ uint32_t pack_bf16(float lo, float hi) {
    __nv_bfloat16 a = __float2bfloat16(lo), b = __float2bfloat16(hi);
    return (uint32_t)__bfloat16_as_ushort(a) | ((uint32_t)__bfloat16_as_ushort(b) << 16);
}

// ---------------- projection GEMM: C = (X @ W + bias) * scale ----------------
__global__ __launch_bounds__(256) void k_proj(const float* __restrict__ X,
                                              const float* __restrict__ W,
                                              const float* __restrict__ bias,
                                              float scale, int which)
{
    __shared__ __align__(16) float As[64 * 17];
    __shared__ __align__(16) float Bs[16 * 64];
    float* C = which ? g_k : g_q;
    int tx = threadIdx.x & 15, ty = threadIdx.x >> 4;
    int r0 = blockIdx.y * 64, c0 = blockIdx.x * 64;
    float acc[4][4] = {};
    for (int k0 = 0; k0 < 768; k0 += 16) {
        int idx = threadIdx.x * 4;
        int ar = idx >> 4, ac = idx & 15;
        float4 av = *(const float4*)&X[(r0 + ar) * 768 + k0 + ac];
        As[ar * 17 + ac + 0] = av.x; As[ar * 17 + ac + 1] = av.y;
        As[ar * 17 + ac + 2] = av.z; As[ar * 17 + ac + 3] = av.w;
        int br_ = idx >> 6, bc = idx & 63;
        *(float4*)&Bs[br_ * 64 + bc] = *(const float4*)&W[(k0 + br_) * 768 + c0 + bc];
        __syncthreads();
#pragma unroll
        for (int kk = 0; kk < 16; kk++) {
            float4 bv = *(float4*)&Bs[kk * 64 + tx * 4];
#pragma unroll
            for (int i = 0; i < 4; i++) {
                float a = As[(ty * 4 + i) * 17 + kk];
                acc[i][0] += a * bv.x; acc[i][1] += a * bv.y;
                acc[i][2] += a * bv.z; acc[i][3] += a * bv.w;
            }
        }
        __syncthreads();
    }
#pragma unroll
    for (int i = 0; i < 4; i++)
#pragma unroll
        for (int j = 0; j < 4; j++) {
            int r = r0 + ty * 4 + i, c = c0 + tx * 4 + j;
            C[r * 768 + c] = (acc[i][j] + bias[c]) * scale;
        }
}

// ---------------- root scores + mask precompute ----------------
__global__ __launch_bounds__(256) void k_root(const float* __restrict__ X,
                                              const float* __restrict__ Wr,
                                              const float* __restrict__ br,
                                              const float* __restrict__ mask)
{
    int warp = (blockIdx.x * blockDim.x + threadIdx.x) >> 5;
    int lane = threadIdx.x & 31;
    if (warp >= BB * LL_) return;
    float s = 0.f;
    for (int t = lane; t < 768; t += 32) s += X[warp * 768 + t] * Wr[t];
#pragma unroll
    for (int o = 16; o > 0; o >>= 1) s += __shfl_down_sync(0xffffffff, s, o);
    if (lane == 0) {
        float m = mask[warp] * (-1.0f / 10000.0f);
        float root = fmaxf(s + br[0] - m * 50.0f, -40.0f);
        g_R[warp] = expf(root);
        g_m[warp] = m;
    }
}

// ---------------- scores -> A = exp(clip(q.k - masks, -40)) ----------------
__global__ __launch_bounds__(256) void k_scores()
{
    int m = blockIdx.z, b = m / HH, h = m % HH;
    int i0 = blockIdx.y * 64, j0 = blockIdx.x * 64;
    __shared__ float Qs[64 * 65];
    __shared__ float Ks[64 * 65];
    const float* qb = g_q + (size_t)b * LL_ * DD;
    const float* kb = g_k + (size_t)b * LL_ * DD;
    for (int t = threadIdx.x; t < 4096; t += 256) {
        int r = t >> 6, c = t & 63;
        Qs[r * 65 + c] = qb[(i0 + r) * DD + h * 64 + c];
        Ks[r * 65 + c] = kb[(j0 + r) * DD + h * 64 + c];
    }
    __syncthreads();
    int tx = threadIdx.x & 15, ty = threadIdx.x >> 4;
    float acc[4][4] = {};
#pragma unroll
    for (int kk = 0; kk < 64; kk++) {
        float bq[4];
#pragma unroll
        for (int j = 0; j < 4; j++) bq[j] = Ks[(tx * 4 + j) * 65 + kk];
#pragma unroll
        for (int i = 0; i < 4; i++) {
            float a = Qs[(ty * 4 + i) * 65 + kk];
#pragma unroll
            for (int j = 0; j < 4; j++) acc[i][j] += a * bq[j];
        }
    }
    float* Am = g_A + (size_t)m * NN * NN;
#pragma unroll
    for (int i = 0; i < 4; i++) {
        int gi = i0 + ty * 4 + i;
        float mi = g_m[b * LL_ + gi];
#pragma unroll
        for (int j = 0; j < 4; j++) {
            int gj = j0 + tx * 4 + j;
            float s = acc[i][j] - 50.0f * (mi + g_m[b * LL_ + gj]);
            s = fmaxf(s, -40.0f);
            Am[gi * NN + gj] = expf(s);
        }
    }
}

// ---------------- column sums of A ----------------
__global__ void k_colsum()
{
    int m = blockIdx.y;
    int j = blockIdx.x * 128 + threadIdx.x;
    const float* Am = g_A + (size_t)m * NN * NN;
    float s = 0.f;
    for (int i = 0; i < NN; i++) s += Am[i * NN + j];
    g_colsum[m * NN + j] = s;
}

// ---------------- build Laplacian LL = diag(colsum + R) - A ----------------
__global__ void k_buildLL()
{
    int idx = blockIdx.x * 256 + threadIdx.x;
    int m = idx / (NN * NN);
    int rem = idx - m * NN * NN;
    int i = rem / NN, j = rem - i * NN;
    float v = -g_A[idx];
    if (i == j) {
        int b = m / HH;
        v += g_colsum[m * NN + j] + g_R[b * LL_ + j];
    }
    g_LLm[idx] = v;
}

// ---------------- blocked Gauss-Jordan inversion, NB=64, 8 steps ----------------
__global__ __launch_bounds__(256) void k_pivot(int kb)
{
    int m = blockIdx.x;
    float* A = g_LLm + (size_t)m * NN * NN;
    float* F = g_Fcol + (size_t)m * NN * 64;
    for (int t = threadIdx.x; t < NN * 64; t += 256) {
        int r = t >> 6, c = t & 63;
        F[t] = A[r * NN + kb * 64 + c];
    }
    __shared__ float P[64 * 65];
    __shared__ float s_col[64];
    __shared__ float s_piv;
    for (int t = threadIdx.x; t < 4096; t += 256) {
        int r = t >> 6, c = t & 63;
        P[r * 65 + c] = A[(kb * 64 + r) * NN + kb * 64 + c];
    }
    __syncthreads();
    for (int k = 0; k < 64; k++) {
        if (threadIdx.x == 0) s_piv = 1.0f / P[k * 65 + k];
        __syncthreads();
        if (threadIdx.x < 64) s_col[threadIdx.x] = P[threadIdx.x * 65 + k];
        __syncthreads();
        if (threadIdx.x < 64) {
            int j = threadIdx.x;
            P[k * 65 + j] = (j == k) ? s_piv : P[k * 65 + j] * s_piv;
        }
        __syncthreads();
        for (int t = threadIdx.x; t < 4096; t += 256) {
            int i = t >> 6, j = t & 63;
            if (i != k) {
                P[i * 65 + j] = (j == k) ? (-s_col[i] * s_piv)
                                         : P[i * 65 + j] - s_col[i] * P[k * 65 + j];
            }
        }
        __syncthreads();
    }
    for (int t = threadIdx.x; t < 4096; t += 256) {
        int r = t >> 6, c = t & 63;
        A[(kb * 64 + r) * NN + kb * 64 + c] = P[r * 65 + c];
    }
}

__global__ __launch_bounds__(256) void k_rowscale(int kb)
{
    int jt = blockIdx.x; if (jt >= kb) jt++;
    int m = blockIdx.y;
    float* A = g_LLm + (size_t)m * NN * NN;
    __shared__ float Ps[64 * 65];
    __shared__ __align__(16) float Ts[64 * 64];
    for (int t = threadIdx.x; t < 4096; t += 256) {
        int r = t >> 6, c = t & 63;
        Ps[r * 65 + c] = A[(kb * 64 + r) * NN + kb * 64 + c];
        Ts[r * 64 + c] = A[(kb * 64 + r) * NN + jt * 64 + c];
    }
    __syncthreads();
    int tx = threadIdx.x & 15, ty = threadIdx.x >> 4;
    float acc[4][4] = {};
#pragma unroll
    for (int kk = 0; kk < 64; kk++) {
        float4 bv = *(float4*)&Ts[kk * 64 + tx * 4];
#pragma unroll
        for (int i = 0; i < 4; i++) {
            float a = Ps[(ty * 4 + i) * 65 + kk];
            acc[i][0] += a * bv.x; acc[i][1] += a * bv.y;
            acc[i][2] += a * bv.z; acc[i][3] += a * bv.w;
        }
    }
#pragma unroll
    for (int i = 0; i < 4; i++)
#pragma unroll
        for (int j = 0; j < 4; j++)
            A[(kb * 64 + ty * 4 + i) * NN + jt * 64 + tx * 4 + j] = acc[i][j];
}

__global__ __launch_bounds__(256) void k_update(int kb)
{
    int jt = blockIdx.x;
    int it = blockIdx.y; if (it >= kb) it++;
    int m = blockIdx.z;
    float* A = g_LLm + (size_t)m * NN * NN;
    const float* F = g_Fcol + (size_t)m * NN * 64;
    __shared__ float Fs[64 * 65];
    __shared__ __align__(16) float Bs[64 * 64];
    for (int t = threadIdx.x; t < 4096; t += 256) {
        int r = t >> 6, c = t & 63;
        Fs[r * 65 + c] = F[(it * 64 + r) * 64 + c];
        Bs[r * 64 + c] = A[(kb * 64 + r) * NN + jt * 64 + c];
    }
    __syncthreads();
    int tx = threadIdx.x & 15, ty = threadIdx.x >> 4;
    float acc[4][4] = {};
#pragma unroll
    for (int kk = 0; kk < 64; kk++) {
        float4 bv = *(float4*)&Bs[kk * 64 + tx * 4];
#pragma unroll
        for (int i = 0; i < 4; i++) {
            float a = Fs[(ty * 4 + i) * 65 + kk];
            acc[i][0] += a * bv.x; acc[i][1] += a * bv.y;
            acc[i][2] += a * bv.z; acc[i][3] += a * bv.w;
        }
    }
#pragma unroll
    for (int i = 0; i < 4; i++)
#pragma unroll
        for (int j = 0; j < 4; j++) {
            int gi = it * 64 + ty * 4 + i, gj = jt * 64 + tx * 4 + j;
            float base = (jt == kb) ? 0.0f : A[gi * NN + gj];
            A[gi * NN + gj] = base - acc[i][j];
        }
}

// ---------------- diag + d0 ----------------
__global__ void k_diag(float* __restrict__ out)
{
    int idx = blockIdx.x * 256 + threadIdx.x;
    int m = idx / NN, i = idx - m * NN;
    float dv = g_LLm[(size_t)m * NN * NN + i * NN + i];
    g_diag[idx] = dv;
    int b = m / HH;
    out[OFF_D0 + idx] = g_R[b * LL_ + i] * dv;
}

// ---------------- d = A * (diag[j] - LLinv[j][i]) ----------------
__global__ void k_dmat(float* __restrict__ out)
{
    int m = blockIdx.z;
    int i0 = blockIdx.y * 32, j0 = blockIdx.x * 32;
    __shared__ float Ts[32 * 33];
    const float* Lm = g_LLm + (size_t)m * NN * NN;
    for (int t = threadIdx.x; t < 1024; t += 256) {
        int r = t >> 5, c = t & 31;
        Ts[r * 33 + c] = Lm[(j0 + r) * NN + i0 + c];
    }
    __syncthreads();
    const float* Am = g_A + (size_t)m * NN * NN;
    float* Dm = out + OFF_D + (size_t)m * NN * NN;
    for (int t = threadIdx.x; t < 1024; t += 256) {
        int li = t >> 5, lj = t & 31;
        int gi = i0 + li, gj = j0 + lj;
        float a = Am[gi * NN + gj];
        Dm[gi * NN + gj] = a * (g_diag[m * NN + gj] - Ts[lj * 33 + li]);
    }
}

// ---------------- context via mma.sync bf16 split (HMMA) ----------------
// C[q, n] = sum_k maskedD[k, q] * x[k, n]  per head m.
// Block tile: 128(q) x 128(n), K-chunk 32. 8 warps, warp tile 32(q) x 64(n).
// fp32 = bf16_hi + bf16_lo; accumulate hi*hi + hi*lo + lo*hi in fp32.
// smem tiles stored [k][col] (k-major rows of 128 bf16 = 256B), XOR-swizzled
// per 16B chunk; ldmatrix.x4.trans produces row-major-A / col-major-B frags.
__global__ __launch_bounds__(256) void k_context_mma(const float* __restrict__ out_d,
                                                     const float* __restrict__ X,
                                                     float* __restrict__ out)
{
    __shared__ __align__(128) uint8_t sAhi[8192];
    __shared__ __align__(128) uint8_t sAlo[8192];
    __shared__ __align__(128) uint8_t sBhi[8192];
    __shared__ __align__(128) uint8_t sBlo[8192];
    __shared__ float sMq[128];

    int t = threadIdx.x;
    int m = blockIdx.z, b = m / HH;
    int q0 = blockIdx.y * 128, n0 = blockIdx.x * 128;
    const float* dm = out_d + OFF_D + (size_t)m * NN * NN;
    const float* xb = X + (size_t)b * LL_ * DD;
    const float* mm = g_m + b * LL_;

    if (t < 128) sMq[t] = mm[q0 + t];

    uint32_t aHi = smem_u32(sAhi), aLo = smem_u32(sAlo);
    uint32_t bHi = smem_u32(sBhi), bLo = smem_u32(sBlo);

    int wid = t >> 5, lane = t & 31;
    int wm = (wid & 3) * 32;    // warp q offset within tile
    int wn = (wid >> 2) * 64;   // warp n offset within tile
    int lrow = (lane & 7) + ((lane >> 4) << 3);  // ldmatrix row within k16
    int lcol8 = (lane & 8) >> 3;                 // ldmatrix chunk col offset

    float c[2][8][4];
#pragma unroll
    for (int i = 0; i < 2; i++)
#pragma unroll
        for (int j = 0; j < 8; j++)
#pragma unroll
            for (int v = 0; v < 4; v++) c[i][j][v] = 0.f;

    __syncthreads();

    for (int kc = 0; kc < 16; kc++) {
        int k0 = kc * 32;
        // ---- fill: 512 chunks of 16B per operand pair; 2 per thread ----
#pragma unroll
        for (int rep = 0; rep < 2; rep++) {
            int id = t + rep * 256;
            int r = id >> 4, ch = id & 15;
            int kg = k0 + r;
            uint32_t off = (uint32_t)(r << 8) + (uint32_t)((ch ^ (r & 7)) << 4);
            // A operand: masked D[kg][q0+ch*8 ..]
            {
                float mk = mm[kg];
                const float* src = dm + (size_t)kg * NN + q0 + ch * 8;
                float4 f0 = *(const float4*)src;
                float4 f1 = *(const float4*)(src + 4);
                float v[8] = {f0.x, f0.y, f0.z, f0.w, f1.x, f1.y, f1.z, f1.w};
#pragma unroll
                for (int i = 0; i < 8; i++)
                    if (mk + sMq[ch * 8 + i] != 0.0f) v[i] = 0.0f;
                uint4 hp, lp;
                uint32_t* hpp = (uint32_t*)&hp;
                uint32_t* lpp = (uint32_t*)&lp;
#pragma unroll
                for (int i = 0; i < 4; i++) {
                    float v0 = v[2 * i], v1 = v[2 * i + 1];
                    __nv_bfloat16 h0 = __float2bfloat16(v0);
                    __nv_bfloat16 h1 = __float2bfloat16(v1);
                    hpp[i] = (uint32_t)__bfloat16_as_ushort(h0) |
                             ((uint32_t)__bfloat16_as_ushort(h1) << 16);
                    lpp[i] = pack_bf16(v0 - __bfloat162float(h0),
                                       v1 - __bfloat162float(h1));
                }
                *(uint4*)(sAhi + off) = hp;
                *(uint4*)(sAlo + off) = lp;
            }
            // B operand: x[kg][n0+ch*8 ..]
            {
                const float* src = xb + (size_t)kg * DD + n0 + ch * 8;
                float4 f0 = *(const float4*)src;
                float4 f1 = *(const float4*)(src + 4);
                float v[8] = {f0.x, f0.y, f0.z, f0.w, f1.x, f1.y, f1.z, f1.w};
                uint4 hp, lp;
                uint32_t* hpp = (uint32_t*)&hp;
                uint32_t* lpp = (uint32_t*)&lp;
#pragma unroll
                for (int i = 0; i < 4; i++) {
                    float v0 = v[2 * i], v1 = v[2 * i + 1];
                    __nv_bfloat16 h0 = __float2bfloat16(v0);
                    __nv_bfloat16 h1 = __float2bfloat16(v1);
                    hpp[i] = (uint32_t)__bfloat16_as_ushort(h0) |
                             ((uint32_t)__bfloat16_as_ushort(h1) << 16);
                    lpp[i] = pack_bf16(v0 - __bfloat162float(h0),
                                       v1 - __bfloat162float(h1));
                }
                *(uint4*)(sBhi + off) = hp;
                *(uint4*)(sBlo + off) = lp;
            }
        }
        __syncthreads();

        // ---- compute: two k16 steps ----
#pragma unroll
        for (int ks = 0; ks < 32; ks += 16) {
            int r = ks + lrow;
            uint32_t rsw = (uint32_t)(r << 8);
            uint32_t rx = (uint32_t)(r & 7);
            uint32_t ah[2][4], al[2][4];
#pragma unroll
            for (int sub = 0; sub < 2; sub++) {
                uint32_t colc = (uint32_t)(((wm + sub * 16) >> 3) + lcol8);
                uint32_t boff = rsw + ((colc ^ rx) << 4);
                ldsm4t(ah[sub], aHi + boff);
                ldsm4t(al[sub], aLo + boff);
            }
            uint32_t bh[4][4], bl[4][4];
#pragma unroll
            for (int ng = 0; ng < 4; ng++) {
                uint32_t colc = (uint32_t)(((wn + ng * 16) >> 3) + lcol8);
                uint32_t boff = rsw + ((colc ^ rx) << 4);
                ldsm4t(bh[ng], bHi + boff);
                ldsm4t(bl[ng], bLo + boff);
            }
#pragma unroll
            for (int sub = 0; sub < 2; sub++) {
#pragma unroll
                for (int nt = 0; nt < 8; nt++) {
                    int ng = nt >> 1, h = nt & 1;
                    uint32_t b0h = bh[ng][h],     b1h = bh[ng][2 + h];
                    uint32_t b0l = bl[ng][h],     b1l = bl[ng][2 + h];
                    mma16816(c[sub][nt], ah[sub], b0h, b1h);
                    mma16816(c[sub][nt], ah[sub], b0l, b1l);
                    mma16816(c[sub][nt], al[sub], b0h, b1h);
                }
            }
        }
        __syncthreads();
    }

    // ---- epilogue ----
    float* Cm = out + OFF_CTX + (size_t)m * LL_ * DD;
#pragma unroll
    for (int sub = 0; sub < 2; sub++) {
        int q = q0 + wm + sub * 16 + (lane >> 2);
#pragma unroll
        for (int nt = 0; nt < 8; nt++) {
            int n = n0 + wn + nt * 8 + (lane & 3) * 2;
            float2 v0 = make_float2(c[sub][nt][0], c[sub][nt][1]);
            float2 v1 = make_float2(c[sub][nt][2], c[sub][nt][3]);
            *(float2*)&Cm[(size_t)q * DD + n] = v0;
            *(float2*)&Cm[(size_t)(q + 8) * DD + n] = v1;
        }
    }
}

// ---------------- BCE loss ----------------
__global__ void k_bce(const float* __restrict__ out, const int* __restrict__ labels)
{
    int idx = blockIdx.x * 256 + threadIdx.x;
    if (idx >= BB * LL_) return;
    int b = idx / LL_, i = idx - b * LL_;
    float y = (float)labels[idx];
    float s = 0.f;
    for (int h = 0; h < HH; h++) {
        float p = out[OFF_D0 + (b * HH + h) * LL_ + i];
        p = fminf(fmaxf(p, 1e-5f), 1.0f - 1e-5f);
        s += -(y * logf(p) + (1.0f - y) * logf(1.0f - p));
    }
    g_bce[idx] = y * s;
}

__global__ void k_loss(float* __restrict__ out)
{
    __shared__ float red[256];
    float s = 0.f;
    for (int t = threadIdx.x; t < BB * LL_; t += 256) s += g_bce[t];
    red[threadIdx.x] = s;
    __syncthreads();
    for (int o = 128; o > 0; o >>= 1) {
        if (threadIdx.x < o) red[threadIdx.x] += red[threadIdx.x + o];
        __syncthreads();
    }
    if (threadIdx.x == 0) out[OFF_LOSS] = red[0] / (float)(BB * LL_);
}

// ---------------- launch ----------------
extern "C" void kernel_launch(void* const* d_in, const int* in_sizes, int n_in,
                              void* d_out, int out_size)
{
    const float* x    = (const float*)d_in[0];
    const float* mask = (const float*)d_in[1];
    const int* roots_label = (const int*)d_in[2];
    const float* Wq = (const float*)d_in[4];
    const float* bq = (const float*)d_in[5];
    const float* Wk = (const float*)d_in[6];
    const float* bk = (const float*)d_in[7];
    const float* Wr = (const float*)d_in[8];
    const float* br = (const float*)d_in[9];
    float* out = (float*)d_out;

    float qscale = 1.0f / sqrtf((float)DD);
    dim3 gproj(12, 64);
    k_proj<<<gproj, 256>>>(x, Wq, bq, qscale, 0);
    k_proj<<<gproj, 256>>>(x, Wk, bk, 1.0f, 1);
    k_root<<<512, 256>>>(x, Wr, br, mask);

    k_scores<<<dim3(8, 8, MTOT), 256>>>();
    k_colsum<<<dim3(4, MTOT), 128>>>();
    k_buildLL<<<(MTOT * NN * NN) / 256, 256>>>();

    for (int kb = 0; kb < 8; kb++) {
        k_pivot<<<MTOT, 256>>>(kb);
        k_rowscale<<<dim3(7, MTOT), 256>>>(kb);
        k_update<<<dim3(8, 7, MTOT), 256>>>(kb);
    }

    k_diag<<<(MTOT * NN) / 256, 256>>>(out);
    k_dmat<<<dim3(16, 16, MTOT), 256>>>(out);
    k_context_mma<<<dim3(6, 4, MTOT), 256>>>(out, x, out);
    k_bce<<<16, 256>>>(out, roots_label);
    k_loss<<<1, 256>>>(out);
}

// round 7
// speedup vs baseline: 1.6581x; 1.6581x over previous
#include <cuda_runtime.h>
#include <cuda_bf16.h>
#include <math.h>
#include <stdint.h>

// Problem dims
#define BB 8
#define LL_ 512
#define DD 768
#define HH 12
#define DKK 64
#define MTOT 96      // BB*HH
#define NN 512

// Output layout (flattened tuple concat)
#define OFF_CTX 0
#define OFF_D   37748736
#define OFF_D0  62914560
#define OFF_LOSS 62963712

// ---------------- scratch (device globals; no allocations allowed) ----------------
__device__ float g_q[BB * LL_ * DD];
__device__ float g_k[BB * LL_ * DD];
__device__ float g_R[BB * LL_];
__device__ float g_m[BB * LL_];
__device__ float g_A[MTOT * NN * NN];     // exp(scores)
__device__ float g_LLm[MTOT * NN * NN];   // Laplacian -> becomes inverse in place
__device__ float g_colsum[MTOT * NN];
__device__ float g_diag[MTOT * NN];
__device__ float g_bce[BB * LL_];
// bf16 split scratch
__device__ __nv_bfloat16 g_dh[MTOT * NN * NN];   // masked d, hi
__device__ __nv_bfloat16 g_dl[MTOT * NN * NN];   // masked d, lo
__device__ __nv_bfloat16 g_xh[BB * LL_ * DD];
__device__ __nv_bfloat16 g_xl[BB * LL_ * DD];
__device__ __nv_bfloat16 g_Fh[MTOT * NN * 64];   // GJ column panel hi
__device__ __nv_bfloat16 g_Fl[MTOT * NN * 64];
__device__ __nv_bfloat16 g_rowh[MTOT * 64 * NN]; // GJ scaled row panel hi
__device__ __nv_bfloat16 g_rowl[MTOT * 64 * NN];

// ===================== mma.sync helpers (HMMA path; compute_103-safe) =====================
__device__ __forceinline__ uint32_t smem_u32(const void* p) {
    uint32_t a;
    asm("{ .reg .u64 t; cvta.to.shared.u64 t, %1; cvt.u32.u64 %0, t; }"
        : "=r"(a) : "l"(p));
    return a;
}

__device__ __forceinline__ void ldsm4(uint32_t* r, uint32_t addr) {
    asm volatile("ldmatrix.sync.aligned.m8n8.x4.shared.b16 {%0,%1,%2,%3}, [%4];"
                 : "=r"(r[0]), "=r"(r[1]), "=r"(r[2]), "=r"(r[3]) : "r"(addr));
}
__device__ __forceinline__ void ldsm4t(uint32_t* r, uint32_t addr) {
    asm volatile("ldmatrix.sync.aligned.m8n8.x4.trans.shared.b16 {%0,%1,%2,%3}, [%4];"
                 : "=r"(r[0]), "=r"(r[1]), "=r"(r[2]), "=r"(r[3]) : "r"(addr));
}

__device__ __forceinline__ void mma16816(float* c, const uint32_t* a,
                                         uint32_t b0, uint32_t b1) {
    asm volatile("mma.sync.aligned.m16n8k16.row.col.f32.bf16.bf16.f32 "
                 "{%0,%1,%2,%3}, {%4,%5,%6,%7}, {%8,%9}, {%0,%1,%2,%3};"
                 : "+f"(c[0]), "+f"(c[1]), "+f"(c[2]), "+f"(c[3])
                 : "r"(a[0]), "r"(a[1]), "r"(a[2]), "r"(a[3]), "r"(b0), "r"(b1));
}

__device__ __forceinline__ void cp16(uint32_t dst, const void* src) {
    asm volatile("{ .reg .u64 g; cvta.to.global.u64 g, %1; "
                 "cp.async.cg.shared.global [%0], [g], 16; }"
                 :: "r"(dst), "l"(src) : "memory");
}
#define CP_COMMIT() asm volatile("cp.async.commit_group;" ::: "memory")
#define CP_WAIT0()  asm volatile("cp.async.wait_group 0;" ::: "memory")

__device__ __forceinline__ void split_bf16(float v, __nv_bfloat16* h, __nv_bfloat16* l) {
    __nv_bfloat16 hh = __float2bfloat16(v);
    *h = hh;
    *l = __float2bfloat16(v - __bfloat162float(hh));
}

// ---------------- projection GEMM: C = (X @ W + bias) * scale ----------------
__global__ __launch_bounds__(256) void k_proj(const float* __restrict__ X,
                                              const float* __restrict__ W,
                                              const float* __restrict__ bias,
                                              float scale, int which)
{
    __shared__ __align__(16) float As[64 * 17];
    __shared__ __align__(16) float Bs[16 * 64];
    float* C = which ? g_k : g_q;
    int tx = threadIdx.x & 15, ty = threadIdx.x >> 4;
    int r0 = blockIdx.y * 64, c0 = blockIdx.x * 64;
    float acc[4][4] = {};
    for (int k0 = 0; k0 < 768; k0 += 16) {
        int idx = threadIdx.x * 4;
        int ar = idx >> 4, ac = idx & 15;
        float4 av = *(const float4*)&X[(r0 + ar) * 768 + k0 + ac];
        As[ar * 17 + ac + 0] = av.x; As[ar * 17 + ac + 1] = av.y;
        As[ar * 17 + ac + 2] = av.z; As[ar * 17 + ac + 3] = av.w;
        int br_ = idx >> 6, bc = idx & 63;
        *(float4*)&Bs[br_ * 64 + bc] = *(const float4*)&W[(k0 + br_) * 768 + c0 + bc];
        __syncthreads();
#pragma unroll
        for (int kk = 0; kk < 16; kk++) {
            float4 bv = *(float4*)&Bs[kk * 64 + tx * 4];
#pragma unroll
            for (int i = 0; i < 4; i++) {
                float a = As[(ty * 4 + i) * 17 + kk];
                acc[i][0] += a * bv.x; acc[i][1] += a * bv.y;
                acc[i][2] += a * bv.z; acc[i][3] += a * bv.w;
            }
        }
        __syncthreads();
    }
#pragma unroll
    for (int i = 0; i < 4; i++)
#pragma unroll
        for (int j = 0; j < 4; j++) {
            int r = r0 + ty * 4 + i, c = c0 + tx * 4 + j;
            C[r * 768 + c] = (acc[i][j] + bias[c]) * scale;
        }
}

// ---------------- root scores + mask precompute ----------------
__global__ __launch_bounds__(256) void k_root(const float* __restrict__ X,
                                              const float* __restrict__ Wr,
                                              const float* __restrict__ br,
                                              const float* __restrict__ mask)
{
    int warp = (blockIdx.x * blockDim.x + threadIdx.x) >> 5;
    int lane = threadIdx.x & 31;
    if (warp >= BB * LL_) return;
    float s = 0.f;
    for (int t = lane; t < 768; t += 32) s += X[warp * 768 + t] * Wr[t];
#pragma unroll
    for (int o = 16; o > 0; o >>= 1) s += __shfl_down_sync(0xffffffff, s, o);
    if (lane == 0) {
        float m = mask[warp] * (-1.0f / 10000.0f);
        float root = fmaxf(s + br[0] - m * 50.0f, -40.0f);
        g_R[warp] = expf(root);
        g_m[warp] = m;
    }
}

// ---------------- x -> bf16 hi/lo ----------------
__global__ void k_xsplit(const float* __restrict__ X)
{
    int idx = blockIdx.x * 256 + threadIdx.x;
    float v = X[idx];
    __nv_bfloat16 h, l;
    split_bf16(v, &h, &l);
    g_xh[idx] = h; g_xl[idx] = l;
}

// ---------------- scores -> A = exp(clip(q.k - masks, -40)) ----------------
__global__ __launch_bounds__(256) void k_scores()
{
    int m = blockIdx.z, b = m / HH, h = m % HH;
    int i0 = blockIdx.y * 64, j0 = blockIdx.x * 64;
    __shared__ float Qs[64 * 65];
    __shared__ float Ks[64 * 65];
    const float* qb = g_q + (size_t)b * LL_ * DD;
    const float* kb = g_k + (size_t)b * LL_ * DD;
    for (int t = threadIdx.x; t < 4096; t += 256) {
        int r = t >> 6, c = t & 63;
        Qs[r * 65 + c] = qb[(i0 + r) * DD + h * 64 + c];
        Ks[r * 65 + c] = kb[(j0 + r) * DD + h * 64 + c];
    }
    __syncthreads();
    int tx = threadIdx.x & 15, ty = threadIdx.x >> 4;
    float acc[4][4] = {};
#pragma unroll
    for (int kk = 0; kk < 64; kk++) {
        float bq[4];
#pragma unroll
        for (int j = 0; j < 4; j++) bq[j] = Ks[(tx * 4 + j) * 65 + kk];
#pragma unroll
        for (int i = 0; i < 4; i++) {
            float a = Qs[(ty * 4 + i) * 65 + kk];
#pragma unroll
            for (int j = 0; j < 4; j++) acc[i][j] += a * bq[j];
        }
    }
    float* Am = g_A + (size_t)m * NN * NN;
#pragma unroll
    for (int i = 0; i < 4; i++) {
        int gi = i0 + ty * 4 + i;
        float mi = g_m[b * LL_ + gi];
#pragma unroll
        for (int j = 0; j < 4; j++) {
            int gj = j0 + tx * 4 + j;
            float s = acc[i][j] - 50.0f * (mi + g_m[b * LL_ + gj]);
            s = fmaxf(s, -40.0f);
            Am[gi * NN + gj] = expf(s);
        }
    }
}

// ---------------- column sums of A ----------------
__global__ void k_colsum()
{
    int m = blockIdx.y;
    int j = blockIdx.x * 128 + threadIdx.x;
    const float* Am = g_A + (size_t)m * NN * NN;
    float s = 0.f;
    for (int i = 0; i < NN; i++) s += Am[i * NN + j];
    g_colsum[m * NN + j] = s;
}

// ---------------- build Laplacian LL = diag(colsum + R) - A ----------------
__global__ void k_buildLL()
{
    int idx = blockIdx.x * 256 + threadIdx.x;
    int m = idx / (NN * NN);
    int rem = idx - m * NN * NN;
    int i = rem / NN, j = rem - i * NN;
    float v = -g_A[idx];
    if (i == j) {
        int b = m / HH;
        v += g_colsum[m * NN + j] + g_R[b * LL_ + j];
    }
    g_LLm[idx] = v;
}

// ---------------- blocked Gauss-Jordan inversion, NB=64, 8 steps ----------------
// step kernel 1: save column panel (bf16 split), invert pivot block in smem,
// write Pinv back (fp32) + its bf16 split into the row-panel buffer.
__global__ __launch_bounds__(256) void k_pivot(int kb)
{
    int m = blockIdx.x;
    float* A = g_LLm + (size_t)m * NN * NN;
    for (int t = threadIdx.x; t < NN * 64; t += 256) {
        int r = t >> 6, c = t & 63;
        float v = A[r * NN + kb * 64 + c];
        __nv_bfloat16 h, l;
        split_bf16(v, &h, &l);
        g_Fh[(size_t)m * NN * 64 + t] = h;
        g_Fl[(size_t)m * NN * 64 + t] = l;
    }
    __shared__ float P[64 * 65];
    __shared__ float s_col[64];
    __shared__ float s_piv;
    for (int t = threadIdx.x; t < 4096; t += 256) {
        int r = t >> 6, c = t & 63;
        P[r * 65 + c] = A[(kb * 64 + r) * NN + kb * 64 + c];
    }
    __syncthreads();
    for (int k = 0; k < 64; k++) {
        if (threadIdx.x == 0) s_piv = 1.0f / P[k * 65 + k];
        __syncthreads();
        if (threadIdx.x < 64) s_col[threadIdx.x] = P[threadIdx.x * 65 + k];
        __syncthreads();
        if (threadIdx.x < 64) {
            int j = threadIdx.x;
            P[k * 65 + j] = (j == k) ? s_piv : P[k * 65 + j] * s_piv;
        }
        __syncthreads();
        for (int t = threadIdx.x; t < 4096; t += 256) {
            int i = t >> 6, j = t & 63;
            if (i != k) {
                P[i * 65 + j] = (j == k) ? (-s_col[i] * s_piv)
                                         : P[i * 65 + j] - s_col[i] * P[k * 65 + j];
            }
        }
        __syncthreads();
    }
    for (int t = threadIdx.x; t < 4096; t += 256) {
        int r = t >> 6, c = t & 63;
        float v = P[r * 65 + c];
        A[(kb * 64 + r) * NN + kb * 64 + c] = v;
        __nv_bfloat16 h, l;
        split_bf16(v, &h, &l);
        g_rowh[(size_t)m * 64 * NN + r * NN + kb * 64 + c] = h;
        g_rowl[(size_t)m * 64 * NN + r * NN + kb * 64 + c] = l;
    }
}

// step kernel 2: row-block scale  A[K][J] = Pinv @ A[K][J]  (J != K), fp32 + bf16 split
__global__ __launch_bounds__(256) void k_rowscale(int kb)
{
    int jt = blockIdx.x; if (jt >= kb) jt++;
    int m = blockIdx.y;
    float* A = g_LLm + (size_t)m * NN * NN;
    __shared__ float Ps[64 * 65];
    __shared__ __align__(16) float Ts[64 * 64];
    for (int t = threadIdx.x; t < 4096; t += 256) {
        int r = t >> 6, c = t & 63;
        Ps[r * 65 + c] = A[(kb * 64 + r) * NN + kb * 64 + c];
        Ts[r * 64 + c] = A[(kb * 64 + r) * NN + jt * 64 + c];
    }
    __syncthreads();
    int tx = threadIdx.x & 15, ty = threadIdx.x >> 4;
    float acc[4][4] = {};
#pragma unroll
    for (int kk = 0; kk < 64; kk++) {
        float4 bv = *(float4*)&Ts[kk * 64 + tx * 4];
#pragma unroll
        for (int i = 0; i < 4; i++) {
            float a = Ps[(ty * 4 + i) * 65 + kk];
            acc[i][0] += a * bv.x; acc[i][1] += a * bv.y;
            acc[i][2] += a * bv.z; acc[i][3] += a * bv.w;
        }
    }
#pragma unroll
    for (int i = 0; i < 4; i++)
#pragma unroll
        for (int j = 0; j < 4; j++) {
            int r = ty * 4 + i, c = jt * 64 + tx * 4 + j;
            float v = acc[i][j];
            A[(kb * 64 + r) * NN + c] = v;
            __nv_bfloat16 h, l;
            split_bf16(v, &h, &l);
            g_rowh[(size_t)m * 64 * NN + r * NN + c] = h;
            g_rowl[(size_t)m * 64 * NN + r * NN + c] = l;
        }
}

// step kernel 3 (HMMA): A[I][J] -= F @ Row[J]; A[I][K] = -F @ Pinv
// 64x64 output tile per block, k=64, 4 warps, 3-term bf16 split.
__global__ __launch_bounds__(128) void k_update_mma(int kb)
{
    __shared__ __align__(128) uint8_t sFh[8192], sFl[8192], sBh[8192], sBl[8192];
    int jt = blockIdx.x;
    int it = blockIdx.y; if (it >= kb) it++;
    int m = blockIdx.z;
    float* A = g_LLm + (size_t)m * NN * NN;
    int t = threadIdx.x;
    int w = t >> 5, lane = t & 31;

    uint32_t fH = smem_u32(sFh), fL = smem_u32(sFl);
    uint32_t bH = smem_u32(sBh), bL = smem_u32(sBl);

    const __nv_bfloat16* Fh = g_Fh + (size_t)m * NN * 64 + (size_t)it * 64 * 64;
    const __nv_bfloat16* Fl = g_Fl + (size_t)m * NN * 64 + (size_t)it * 64 * 64;
    const __nv_bfloat16* Rh = g_rowh + (size_t)m * 64 * NN + jt * 64;
    const __nv_bfloat16* Rl = g_rowl + (size_t)m * 64 * NN + jt * 64;

    for (int id = t; id < 512; id += 128) {
        int r = id >> 3, ch = id & 7;
        uint32_t off = (uint32_t)(r << 7) + (uint32_t)((ch ^ (r & 7)) << 4);
        cp16(fH + off, Fh + r * 64 + ch * 8);
        cp16(fL + off, Fl + r * 64 + ch * 8);
        cp16(bH + off, Rh + (size_t)r * NN + ch * 8);
        cp16(bL + off, Rl + (size_t)r * NN + ch * 8);
    }
    CP_COMMIT(); CP_WAIT0();
    __syncthreads();

    int lrow = (lane & 7) + ((lane >> 4) << 3);
    int lcol8 = (lane & 8) >> 3;

    float c[8][4];
#pragma unroll
    for (int i = 0; i < 8; i++)
#pragma unroll
        for (int v = 0; v < 4; v++) c[i][v] = 0.f;

#pragma unroll
    for (int ks = 0; ks < 4; ks++) {
        uint32_t ah[4], al[4];
        {
            int arow = (w << 4) + (lane & 7) + (lane & 8);
            int ac8 = (ks << 1) + (lane >> 4);
            uint32_t aoff = (uint32_t)(arow << 7) + (uint32_t)((ac8 ^ (arow & 7)) << 4);
            ldsm4(ah, fH + aoff);
            ldsm4(al, fL + aoff);
        }
        uint32_t bhf[4][4], blf[4][4];
        int r = (ks << 4) + lrow;
        int rx = r & 7;
#pragma unroll
        for (int ng = 0; ng < 4; ng++) {
            int colc = (ng << 1) + lcol8;
            uint32_t boff = (uint32_t)(r << 7) + (uint32_t)((colc ^ rx) << 4);
            ldsm4t(bhf[ng], bH + boff);
            ldsm4t(blf[ng], bL + boff);
        }
#pragma unroll
        for (int ng = 0; ng < 4; ng++)
#pragma unroll
            for (int h = 0; h < 2; h++) {
                int nt = ng * 2 + h;
                mma16816(c[nt], ah, bhf[ng][h], bhf[ng][2 + h]);
                mma16816(c[nt], ah, blf[ng][h], blf[ng][2 + h]);
                mma16816(c[nt], al, bhf[ng][h], bhf[ng][2 + h]);
            }
    }

    // epilogue: C = base - acc (base = 0 for jt == kb)
    int row = it * 64 + (w << 4) + (lane >> 2);
    int coff = (lane & 3) * 2;
#pragma unroll
    for (int nt = 0; nt < 8; nt++) {
        int col = jt * 64 + nt * 8 + coff;
        float* p0 = &A[(size_t)row * NN + col];
        float* p1 = &A[(size_t)(row + 8) * NN + col];
        float2 b0 = make_float2(0.f, 0.f), b1 = make_float2(0.f, 0.f);
        if (jt != kb) { b0 = *(float2*)p0; b1 = *(float2*)p1; }
        *(float2*)p0 = make_float2(b0.x - c[nt][0], b0.y - c[nt][1]);
        *(float2*)p1 = make_float2(b1.x - c[nt][2], b1.y - c[nt][3]);
    }
}

// ---------------- diag + d0 ----------------
__global__ void k_diag(float* __restrict__ out)
{
    int idx = blockIdx.x * 256 + threadIdx.x;
    int m = idx / NN, i = idx - m * NN;
    float dv = g_LLm[(size_t)m * NN * NN + i * NN + i];
    g_diag[idx] = dv;
    int b = m / HH;
    out[OFF_D0 + idx] = g_R[b * LL_ + i] * dv;
}

// ---------------- d = A * (diag[j] - LLinv[j][i]); also masked bf16 split ----------------
__global__ void k_dmat(float* __restrict__ out)
{
    int m = blockIdx.z, b = m / HH;
    int i0 = blockIdx.y * 32, j0 = blockIdx.x * 32;
    __shared__ float Ts[32 * 33];
    __shared__ float mi_s[32], mj_s[32];
    const float* Lm = g_LLm + (size_t)m * NN * NN;
    if (threadIdx.x < 32) mi_s[threadIdx.x] = g_m[b * LL_ + i0 + threadIdx.x];
    else if (threadIdx.x < 64) mj_s[threadIdx.x - 32] = g_m[b * LL_ + j0 + threadIdx.x - 32];
    for (int t = threadIdx.x; t < 1024; t += 256) {
        int r = t >> 5, c = t & 31;
        Ts[r * 33 + c] = Lm[(j0 + r) * NN + i0 + c];
    }
    __syncthreads();
    const float* Am = g_A + (size_t)m * NN * NN;
    float* Dm = out + OFF_D + (size_t)m * NN * NN;
    for (int t = threadIdx.x; t < 1024; t += 256) {
        int li = t >> 5, lj = t & 31;
        int gi = i0 + li, gj = j0 + lj;
        float a = Am[gi * NN + gj];
        float v = a * (g_diag[m * NN + gj] - Ts[lj * 33 + li]);
        Dm[gi * NN + gj] = v;
        float vm = (mi_s[li] + mj_s[lj] != 0.0f) ? 0.0f : v;
        size_t idx = (size_t)m * NN * NN + (size_t)gi * NN + gj;
        __nv_bfloat16 h, l;
        split_bf16(vm, &h, &l);
        g_dh[idx] = h; g_dl[idx] = l;
    }
}

// ---------------- context via mma.sync bf16 split (pre-split operands) ----------------
// C[q, n] = sum_k maskedD[k, q] * x[k, n]  per head m.
// Block tile: 128(q) x 128(n), K-chunk 32. 8 warps, warp tile 32(q) x 64(n).
__global__ __launch_bounds__(256) void k_context_mma(float* __restrict__ out)
{
    __shared__ __align__(128) uint8_t sAhi[8192], sAlo[8192], sBhi[8192], sBlo[8192];
    int t = threadIdx.x;
    int m = blockIdx.z, b = m / HH;
    int q0 = blockIdx.y * 128, n0 = blockIdx.x * 128;
    const __nv_bfloat16* dh = g_dh + (size_t)m * NN * NN;
    const __nv_bfloat16* dl = g_dl + (size_t)m * NN * NN;
    const __nv_bfloat16* xh = g_xh + (size_t)b * LL_ * DD;
    const __nv_bfloat16* xl = g_xl + (size_t)b * LL_ * DD;

    uint32_t aHi = smem_u32(sAhi), aLo = smem_u32(sAlo);
    uint32_t bHi = smem_u32(sBhi), bLo = smem_u32(sBlo);

    int wid = t >> 5, lane = t & 31;
    int wm = (wid & 3) * 32;
    int wn = (wid >> 2) * 64;
    int lrow = (lane & 7) + ((lane >> 4) << 3);
    int lcol8 = (lane & 8) >> 3;

    float c[2][8][4];
#pragma unroll
    for (int i = 0; i < 2; i++)
#pragma unroll
        for (int j = 0; j < 8; j++)
#pragma unroll
            for (int v = 0; v < 4; v++) c[i][j][v] = 0.f;

    for (int kc = 0; kc < 16; kc++) {
        int k0 = kc * 32;
#pragma unroll
        for (int rep = 0; rep < 2; rep++) {
            int id = t + rep * 256;
            int r = id >> 4, ch = id & 15;
            int kg = k0 + r;
            uint32_t off = (uint32_t)(r << 8) + (uint32_t)((ch ^ (r & 7)) << 4);
            cp16(aHi + off, dh + (size_t)kg * NN + q0 + ch * 8);
            cp16(aLo + off, dl + (size_t)kg * NN + q0 + ch * 8);
            cp16(bHi + off, xh + (size_t)kg * DD + n0 + ch * 8);
            cp16(bLo + off, xl + (size_t)kg * DD + n0 + ch * 8);
        }
        CP_COMMIT(); CP_WAIT0();
        __syncthreads();

#pragma unroll
        for (int ks = 0; ks < 32; ks += 16) {
            int r = ks + lrow;
            uint32_t rsw = (uint32_t)(r << 8);
            uint32_t rx = (uint32_t)(r & 7);
            uint32_t ah[2][4], al[2][4];
#pragma unroll
            for (int sub = 0; sub < 2; sub++) {
                uint32_t colc = (uint32_t)(((wm + sub * 16) >> 3) + lcol8);
                uint32_t boff = rsw + ((colc ^ rx) << 4);
                ldsm4t(ah[sub], aHi + boff);
                ldsm4t(al[sub], aLo + boff);
            }
            uint32_t bh[4][4], bl[4][4];
#pragma unroll
            for (int ng = 0; ng < 4; ng++) {
                uint32_t colc = (uint32_t)(((wn + ng * 16) >> 3) + lcol8);
                uint32_t boff = rsw + ((colc ^ rx) << 4);
                ldsm4t(bh[ng], bHi + boff);
                ldsm4t(bl[ng], bLo + boff);
            }
#pragma unroll
            for (int sub = 0; sub < 2; sub++) {
#pragma unroll
                for (int nt = 0; nt < 8; nt++) {
                    int ng = nt >> 1, h = nt & 1;
                    uint32_t b0h = bh[ng][h], b1h = bh[ng][2 + h];
                    uint32_t b0l = bl[ng][h], b1l = bl[ng][2 + h];
                    mma16816(c[sub][nt], ah[sub], b0h, b1h);
                    mma16816(c[sub][nt], ah[sub], b0l, b1l);
                    mma16816(c[sub][nt], al[sub], b0h, b1h);
                }
            }
        }
        __syncthreads();
    }

    float* Cm = out + OFF_CTX + (size_t)m * LL_ * DD;
#pragma unroll
    for (int sub = 0; sub < 2; sub++) {
        int q = q0 + wm + sub * 16 + (lane >> 2);
#pragma unroll
        for (int nt = 0; nt < 8; nt++) {
            int n = n0 + wn + nt * 8 + (lane & 3) * 2;
            *(float2*)&Cm[(size_t)q * DD + n] = make_float2(c[sub][nt][0], c[sub][nt][1]);
            *(float2*)&Cm[(size_t)(q + 8) * DD + n] = make_float2(c[sub][nt][2], c[sub][nt][3]);
        }
    }
}

// ---------------- BCE loss ----------------
__global__ void k_bce(const float* __restrict__ out, const int* __restrict__ labels)
{
    int idx = blockIdx.x * 256 + threadIdx.x;
    if (idx >= BB * LL_) return;
    int b = idx / LL_, i = idx - b * LL_;
    float y = (float)labels[idx];
    float s = 0.f;
    for (int h = 0; h < HH; h++) {
        float p = out[OFF_D0 + (b * HH + h) * LL_ + i];
        p = fminf(fmaxf(p, 1e-5f), 1.0f - 1e-5f);
        s += -(y * logf(p) + (1.0f - y) * logf(1.0f - p));
    }
    g_bce[idx] = y * s;
}

__global__ void k_loss(float* __restrict__ out)
{
    __shared__ float red[256];
    float s = 0.f;
    for (int t = threadIdx.x; t < BB * LL_; t += 256) s += g_bce[t];
    red[threadIdx.x] = s;
    __syncthreads();
    for (int o = 128; o > 0; o >>= 1) {
        if (threadIdx.x < o) red[threadIdx.x] += red[threadIdx.x + o];
        __syncthreads();
    }
    if (threadIdx.x == 0) out[OFF_LOSS] = red[0] / (float)(BB * LL_);
}

// ---------------- launch ----------------
extern "C" void kernel_launch(void* const* d_in, const int* in_sizes, int n_in,
                              void* d_out, int out_size)
{
    const float* x    = (const float*)d_in[0];
    const float* mask = (const float*)d_in[1];
    const int* roots_label = (const int*)d_in[2];
    const float* Wq = (const float*)d_in[4];
    const float* bq = (const float*)d_in[5];
    const float* Wk = (const float*)d_in[6];
    const float* bk = (const float*)d_in[7];
    const float* Wr = (const float*)d_in[8];
    const float* br = (const float*)d_in[9];
    float* out = (float*)d_out;

    float qscale = 1.0f / sqrtf((float)DD);
    dim3 gproj(12, 64);
    k_proj<<<gproj, 256>>>(x, Wq, bq, qscale, 0);
    k_proj<<<gproj, 256>>>(x, Wk, bk, 1.0f, 1);
    k_root<<<512, 256>>>(x, Wr, br, mask);
    k_xsplit<<<(BB * LL_ * DD) / 256, 256>>>(x);

    k_scores<<<dim3(8, 8, MTOT), 256>>>();
    k_colsum<<<dim3(4, MTOT), 128>>>();
    k_buildLL<<<(MTOT * NN * NN) / 256, 256>>>();

    for (int kb = 0; kb < 8; kb++) {
        k_pivot<<<MTOT, 256>>>(kb);
        k_rowscale<<<dim3(7, MTOT), 256>>>(kb);
        k_update_mma<<<dim3(8, 7, MTOT), 128>>>(kb);
    }

    k_diag<<<(MTOT * NN) / 256, 256>>>(out);
    k_dmat<<<dim3(16, 16, MTOT), 256>>>(out);
    k_context_mma<<<dim3(6, 4, MTOT), 256>>>(out);
    k_bce<<<16, 256>>>(out, roots_label);
    k_loss<<<1, 256>>>(out);
}